// round 7
// baseline (speedup 1.0000x reference)
#include <cuda_runtime.h>
#include <cuda_fp16.h>
#include <cstdint>
#include <cstddef>

// ---------------- problem constants ----------------
static constexpr int GQ   = 8;
static constexpr int HDIM = 4096;
static constexpr int IDIM = 1536;
static constexpr int MTOT = 16384;
static constexpr int MG   = MTOT / GQ;        // 2048

// ---------------- tiling ----------------
static constexpr int TILE_M = 64;             // rows per CTA
static constexpr int TILE_J = 96;             // output cols per CTA
static constexpr int BROWS  = 2 * TILE_J;     // 192 w-rows (gate/up interleaved)
static constexpr int TILE_K = 64;             // fp16 -> 128B rows
static constexpr int STAGES = 3;
static constexpr int NITER  = HDIM / TILE_K;  // 64
static constexpr int MT     = MG / TILE_M;    // 32
static constexpr int NT     = IDIM / TILE_J;  // 16

static constexpr int A_BYTES     = TILE_M * TILE_K * 2;   // 8 KB
static constexpr int B_BYTES     = BROWS  * TILE_K * 2;   // 24 KB
static constexpr int STAGE_BYTES = A_BYTES + B_BYTES;     // 32 KB
static constexpr int SMEM_TOTAL  = STAGES * STAGE_BYTES;  // 96 KB -> 2 CTAs/SM
static constexpr int THREADS     = 256;                   // 8 warps: 2m x 4n

// ---------------- scratch: fp16 (RN) copies of inputs ----------------
__device__ __half g_xh[(size_t)MTOT * HDIM];               // 128 MB
__device__ __half g_wh[(size_t)GQ * 2 * IDIM * HDIM];      // 192 MB

// ---------------- PTX helpers (base sm_103: no tcgen05) ----------------
__device__ __forceinline__ uint32_t smem_u32(const void* p) {
    uint32_t a;
    asm("{ .reg .u64 t; cvta.to.shared.u64 t, %1; cvt.u32.u64 %0, t; }" : "=r"(a) : "l"(p));
    return a;
}
__device__ __forceinline__ void cp_async16(uint32_t dst, const void* src) {
    asm volatile("cp.async.cg.shared.global [%0], [%1], 16;" :: "r"(dst), "l"(src));
}
__device__ __forceinline__ void cp_commit() {
    asm volatile("cp.async.commit_group;" ::: "memory");
}
__device__ __forceinline__ void cp_wait1() {
    asm volatile("cp.async.wait_group 1;" ::: "memory");
}
__device__ __forceinline__ void ldsm4(uint32_t* r, uint32_t addr) {
    asm volatile("ldmatrix.sync.aligned.m8n8.x4.shared.b16 {%0,%1,%2,%3}, [%4];"
                 : "=r"(r[0]), "=r"(r[1]), "=r"(r[2]), "=r"(r[3]) : "r"(addr));
}
__device__ __forceinline__ void mma16(float* d, const uint32_t* a, uint32_t b0, uint32_t b1) {
    asm volatile(
        "mma.sync.aligned.m16n8k16.row.col.f32.f16.f16.f32 "
        "{%0,%1,%2,%3}, {%4,%5,%6,%7}, {%8,%9}, {%0,%1,%2,%3};"
        : "+f"(d[0]), "+f"(d[1]), "+f"(d[2]), "+f"(d[3])
        : "r"(a[0]), "r"(a[1]), "r"(a[2]), "r"(a[3]), "r"(b0), "r"(b1));
}
__device__ __forceinline__ float silu_mul(float g, float u) {
    return g * u / (1.0f + __expf(-g));
}

// ---------------- prepass: fp32 -> fp16 (RN), both tensors in ONE kernel ----------------
__global__ void cvt_f16_kernel(const float4* __restrict__ x, __half* __restrict__ xh, int nx4,
                               const float4* __restrict__ w, __half* __restrict__ wh, int nw4) {
    int i = blockIdx.x * blockDim.x + threadIdx.x;
    const int stride = gridDim.x * blockDim.x;
    const int ntot = nx4 + nw4;
    for (; i < ntot; i += stride) {
        float4 v;
        __half* dst;
        if (i < nx4) { v = x[i]; dst = xh + (size_t)i * 4; }
        else         { v = w[i - nx4]; dst = wh + (size_t)(i - nx4) * 4; }
        __half2 lo = __floats2half2_rn(v.x, v.y);
        __half2 hi = __floats2half2_rn(v.z, v.w);
        uint2 pk;
        pk.x = *reinterpret_cast<uint32_t*>(&lo);
        pk.y = *reinterpret_cast<uint32_t*>(&hi);
        *reinterpret_cast<uint2*>(dst) = pk;
    }
}

// ---------------- fused grouped GEMM + SwiGLU (fp16 in, fp32 accum) ----------------
__global__ void __launch_bounds__(THREADS, 2)
swiglu_kernel(const __half* __restrict__ x, const __half* __restrict__ w,
              float* __restrict__ out) {
    extern __shared__ char smem[];
    const uint32_t sb = smem_u32(smem);

    const int tid  = threadIdx.x;
    const int lane = tid & 31;
    const int wid  = tid >> 5;
    const int wm   = wid >> 2;   // 0..1 (32 m-rows)
    const int wn   = wid & 3;    // 0..3 (48 B-rows = 24 out-cols)

    const int bx = blockIdx.x;
    const int g  = bx / (MT * NT);
    const int r2 = bx % (MT * NT);
    const int mt = r2 / NT;
    const int nt = r2 % NT;

    const size_t m0 = (size_t)g * MG + (size_t)mt * TILE_M;
    const int    n0 = nt * TILE_J;

    const __half* Ax = x + m0 * HDIM;
    const __half* Wg = w + ((size_t)g * (2 * IDIM) + (size_t)n0) * HDIM;

    // ---- per-thread cp.async descriptors (swizzle layout verified R2/R6) ----
    // A: 64 rows x 8 segs = 512 segs -> 2 per thread
    uint32_t dA[2], oA[2];
    #pragma unroll
    for (int t = 0; t < 2; ++t) {
        const int c = tid + THREADS * t;     // 0..511
        const int m = c >> 3, s = c & 7;
        dA[t] = (uint32_t)((((m >> 3) * 8 + s) << 7) + (((m & 7) ^ s) << 4));
        oA[t] = (uint32_t)(m * HDIM + s * 8);
    }
    // B: 192 interleaved rows x 8 segs = 1536 segs -> 6 per thread
    uint32_t dB[6], oB[6];
    #pragma unroll
    for (int t = 0; t < 6; ++t) {
        const int c  = tid + THREADS * t;    // 0..1535
        const int rr = c >> 3, s = c & 7;
        const int j  = rr >> 1;              // even = gate j, odd = up j
        dB[t] = (uint32_t)(A_BYTES + (((rr >> 3) * 8 + s) << 7) + (((rr & 7) ^ s) << 4));
        oB[t] = (uint32_t)(j * HDIM + s * 8 + ((rr & 1) ? IDIM * HDIM : 0));
    }

    // ---- per-lane ldmatrix terms ----
    const int quad = lane >> 3;
    const int row  = lane & 7;
    // A: warp covers 32 rows = 4 x 1KB row-blocks
    const uint32_t mterm0 = (uint32_t)((wm * 4 + (quad & 1)) << 10);
    uint32_t ktA[4];
    #pragma unroll
    for (int ks = 0; ks < 4; ++ks) {
        const int kb = 2 * ks + (quad >> 1);
        ktA[ks] = (uint32_t)((kb << 7) + ((row ^ kb) << 4));
    }
    // B: warp covers 48 B-rows = 6 n8-frags = 3 ldsm.x4 groups
    const uint32_t nterm0 = (uint32_t)(A_BYTES + ((wn * 6 + (quad >> 1)) << 10));
    uint32_t ktB[4];
    #pragma unroll
    for (int ks = 0; ks < 4; ++ks) {
        const int kb = 2 * ks + (quad & 1);
        ktB[ks] = (uint32_t)((kb << 7) + ((row ^ kb) << 4));
    }

    float acc[48];
    #pragma unroll
    for (int i = 0; i < 48; ++i) acc[i] = 0.0f;

    // ---- prologue: fill stages 0,1 ----
    #pragma unroll
    for (int s = 0; s < STAGES - 1; ++s) {
        const uint32_t st = sb + (uint32_t)(s * STAGE_BYTES);
        const __half* a = Ax + s * TILE_K;
        const __half* b = Wg + s * TILE_K;
        #pragma unroll
        for (int t = 0; t < 2; ++t) cp_async16(st + dA[t], a + oA[t]);
        #pragma unroll
        for (int t = 0; t < 6; ++t) cp_async16(st + dB[t], b + oB[t]);
        cp_commit();
    }

    // ---- mainloop (3-slot ring, slots tracked without %) ----
    int sc = 0;   // compute slot
    int sw = 2;   // write slot
    #pragma unroll 1
    for (int i = 0; i < NITER; ++i) {
        cp_wait1();          // compute slot resident (own warp's copies)
        __syncthreads();     // cross-warp visibility; prior reads of write slot done

        if (i + STAGES - 1 < NITER) {
            const int it = i + STAGES - 1;
            const uint32_t stw = sb + (uint32_t)(sw * STAGE_BYTES);
            const __half* a = Ax + it * TILE_K;
            const __half* b = Wg + it * TILE_K;
            #pragma unroll
            for (int t = 0; t < 2; ++t) cp_async16(stw + dA[t], a + oA[t]);
            #pragma unroll
            for (int t = 0; t < 6; ++t) cp_async16(stw + dB[t], b + oB[t]);
        }
        cp_commit();

        const uint32_t st = sb + (uint32_t)(sc * STAGE_BYTES);
        #pragma unroll
        for (int ks = 0; ks < 4; ++ks) {
            uint32_t afr[8], bfr[12];
            #pragma unroll
            for (int f = 0; f < 2; ++f)      // 2 m16-frags (32 rows)
                ldsm4(&afr[4 * f], st + mterm0 + (uint32_t)(f << 11) + ktA[ks]);
            #pragma unroll
            for (int gg = 0; gg < 3; ++gg)   // 6 n8-frags (48 B-rows)
                ldsm4(&bfr[4 * gg], st + nterm0 + (uint32_t)(gg << 11) + ktB[ks]);
            #pragma unroll
            for (int f = 0; f < 2; ++f) {
                #pragma unroll
                for (int nf = 0; nf < 6; ++nf) {
                    const int bo = ((nf >> 1) << 2) + ((nf & 1) << 1);
                    mma16(&acc[(f * 6 + nf) * 4], &afr[4 * f], bfr[bo], bfr[bo + 1]);
                }
            }
        }
        sc = (sc == 2) ? 0 : sc + 1;
        sw = (sw == 2) ? 0 : sw + 1;
    }

    __syncthreads();

    // ---- epilogue: silu(gate)*up, direct global stores ----
    const int gid = lane >> 2;
    const int tg  = lane & 3;
    #pragma unroll
    for (int f = 0; f < 2; ++f) {
        #pragma unroll
        for (int nf = 0; nf < 6; ++nf) {
            const float* c = &acc[(f * 6 + nf) * 4];
            const size_t mg1 = m0 + (size_t)(wm * 32 + f * 16 + gid);
            const int    jg  = n0 + wn * 24 + nf * 4 + tg;
            out[mg1 * IDIM + jg]       = silu_mul(c[0], c[1]);
            out[(mg1 + 8) * IDIM + jg] = silu_mul(c[2], c[3]);
        }
    }
}

// ---------------- launch ----------------
extern "C" void kernel_launch(void* const* d_in, const int* in_sizes, int n_in,
                              void* d_out, int out_size) {
    const float* x = (const float*)d_in[0];
    const float* w = (const float*)d_in[1];
    float* out = (float*)d_out;

    void* pxh = nullptr;
    void* pwh = nullptr;
    cudaGetSymbolAddress(&pxh, g_xh);
    cudaGetSymbolAddress(&pwh, g_wh);

    const int nx4 = (int)(((size_t)MTOT * HDIM) / 4);
    const int nw4 = (int)(((size_t)GQ * 2 * IDIM * HDIM) / 4);
    cvt_f16_kernel<<<2048, 256>>>((const float4*)x, (__half*)pxh, nx4,
                                  (const float4*)w, (__half*)pwh, nw4);

    cudaFuncSetAttribute(swiglu_kernel,
                         cudaFuncAttributeMaxDynamicSharedMemorySize, SMEM_TOTAL);
    swiglu_kernel<<<GQ * MT * NT, THREADS, SMEM_TOTAL>>>(
        (const __half*)pxh, (const __half*)pwh, out);
}

// round 8
// speedup vs baseline: 1.1998x; 1.1998x over previous
#include <cuda_runtime.h>
#include <cuda_fp16.h>
#include <cstdint>
#include <cstddef>

// ---------------- problem constants ----------------
static constexpr int GQ   = 8;
static constexpr int HDIM = 4096;
static constexpr int IDIM = 1536;
static constexpr int MTOT = 16384;
static constexpr int MG   = MTOT / GQ;        // 2048

// ---------------- tiling (R6 shape: best so far) ----------------
static constexpr int TILE_M = 128;            // rows per CTA
static constexpr int TILE_J = 128;            // output cols per CTA
static constexpr int BROWS  = 2 * TILE_J;     // 256 w-rows (gate/up interleaved)
static constexpr int TILE_K = 64;             // fp16 -> 128B rows
static constexpr int STAGES = 4;
static constexpr int NITER  = HDIM / TILE_K;  // 64
static constexpr int MT     = MG / TILE_M;    // 16
static constexpr int NT     = IDIM / TILE_J;  // 12

static constexpr int A_BYTES     = TILE_M * TILE_K * 2;   // 16 KB
static constexpr int B_BYTES     = BROWS  * TILE_K * 2;   // 32 KB
static constexpr int STAGE_BYTES = A_BYTES + B_BYTES;     // 48 KB
static constexpr int SMEM_TOTAL  = STAGES * STAGE_BYTES;  // 192 KB
static constexpr int THREADS     = 256;                   // 8 warps: 2m x 4n

// ---------------- scratch: fp16 (RN) copies of inputs ----------------
__device__ __half g_xh[(size_t)MTOT * HDIM];               // 128 MB
__device__ __half g_wh[(size_t)GQ * 2 * IDIM * HDIM];      // 192 MB

// ---------------- PTX helpers (base sm_103: no tcgen05) ----------------
__device__ __forceinline__ uint32_t smem_u32(const void* p) {
    uint32_t a;
    asm("{ .reg .u64 t; cvta.to.shared.u64 t, %1; cvt.u32.u64 %0, t; }" : "=r"(a) : "l"(p));
    return a;
}
__device__ __forceinline__ void cp_async16(uint32_t dst, const void* src) {
    asm volatile("cp.async.cg.shared.global [%0], [%1], 16;" :: "r"(dst), "l"(src));
}
__device__ __forceinline__ void cp_commit() {
    asm volatile("cp.async.commit_group;" ::: "memory");
}
__device__ __forceinline__ void cp_wait1() {
    asm volatile("cp.async.wait_group 1;" ::: "memory");
}
// NON-volatile, but with "memory" clobber: cannot cross barriers/waits,
// CAN be interleaved/reordered with MMAs by ptxas between barriers.
__device__ __forceinline__ void ldsm4(uint32_t* r, uint32_t addr) {
    asm("ldmatrix.sync.aligned.m8n8.x4.shared.b16 {%0,%1,%2,%3}, [%4];"
        : "=r"(r[0]), "=r"(r[1]), "=r"(r[2]), "=r"(r[3]) : "r"(addr) : "memory");
}
// NON-volatile pure register op: register deps carry ordering; ptxas schedules.
__device__ __forceinline__ void mma16(float* d, const uint32_t* a, uint32_t b0, uint32_t b1) {
    asm("mma.sync.aligned.m16n8k16.row.col.f32.f16.f16.f32 "
        "{%0,%1,%2,%3}, {%4,%5,%6,%7}, {%8,%9}, {%0,%1,%2,%3};"
        : "+f"(d[0]), "+f"(d[1]), "+f"(d[2]), "+f"(d[3])
        : "r"(a[0]), "r"(a[1]), "r"(a[2]), "r"(a[3]), "r"(b0), "r"(b1));
}
__device__ __forceinline__ float silu_mul(float g, float u) {
    return g * u / (1.0f + __expf(-g));
}

// ---------------- prepass: fp32 -> fp16 (RN), both tensors in ONE kernel ----------------
__global__ void cvt_f16_kernel(const float4* __restrict__ x, __half* __restrict__ xh, int nx4,
                               const float4* __restrict__ w, __half* __restrict__ wh, int nw4) {
    int i = blockIdx.x * blockDim.x + threadIdx.x;
    const int stride = gridDim.x * blockDim.x;
    const int ntot = nx4 + nw4;
    for (; i < ntot; i += stride) {
        float4 v;
        __half* dst;
        if (i < nx4) { v = x[i]; dst = xh + (size_t)i * 4; }
        else         { v = w[i - nx4]; dst = wh + (size_t)(i - nx4) * 4; }
        __half2 lo = __floats2half2_rn(v.x, v.y);
        __half2 hi = __floats2half2_rn(v.z, v.w);
        uint2 pk;
        pk.x = *reinterpret_cast<uint32_t*>(&lo);
        pk.y = *reinterpret_cast<uint32_t*>(&hi);
        *reinterpret_cast<uint2*>(dst) = pk;
    }
}

// ---------------- fused grouped GEMM + SwiGLU (fp16 in, fp32 accum) ----------------
__global__ void __launch_bounds__(THREADS, 1)
swiglu_kernel(const __half* __restrict__ x, const __half* __restrict__ w,
              float* __restrict__ out) {
    extern __shared__ char smem[];
    const uint32_t sb = smem_u32(smem);

    const int tid  = threadIdx.x;
    const int lane = tid & 31;
    const int wid  = tid >> 5;
    const int wm   = wid >> 2;   // 0..1 (64 m-rows)
    const int wn   = wid & 3;    // 0..3 (64 B-rows = 32 out-cols)

    const int bx = blockIdx.x;
    const int g  = bx / (MT * NT);
    const int r2 = bx % (MT * NT);
    const int mt = r2 / NT;
    const int nt = r2 % NT;

    const size_t m0 = (size_t)g * MG + (size_t)mt * TILE_M;
    const int    n0 = nt * TILE_J;

    const __half* Ax = x + m0 * HDIM;
    const __half* Wg = w + ((size_t)g * (2 * IDIM) + (size_t)n0) * HDIM;

    // ---- per-thread cp.async descriptors (swizzle verified R2/R6) ----
    uint32_t dA[4], oA[4];
    #pragma unroll
    for (int t = 0; t < 4; ++t) {
        const int c = tid + THREADS * t;     // 0..1023
        const int m = c >> 3, s = c & 7;
        dA[t] = (uint32_t)((((m >> 3) * 8 + s) << 7) + (((m & 7) ^ s) << 4));
        oA[t] = (uint32_t)(m * HDIM + s * 8);
    }
    uint32_t dB[8], oB[8];
    #pragma unroll
    for (int t = 0; t < 8; ++t) {
        const int c  = tid + THREADS * t;    // 0..2047
        const int rr = c >> 3, s = c & 7;
        const int j  = rr >> 1;              // even = gate j, odd = up j
        dB[t] = (uint32_t)(A_BYTES + (((rr >> 3) * 8 + s) << 7) + (((rr & 7) ^ s) << 4));
        oB[t] = (uint32_t)(j * HDIM + s * 8 + ((rr & 1) ? IDIM * HDIM : 0));
    }

    // ---- per-lane ldmatrix terms ----
    const int quad = lane >> 3;
    const int row  = lane & 7;
    const uint32_t mterm0 = (uint32_t)((wm * 8 + (quad & 1)) << 10);
    uint32_t ktA[4];
    #pragma unroll
    for (int ks = 0; ks < 4; ++ks) {
        const int kb = 2 * ks + (quad >> 1);
        ktA[ks] = (uint32_t)((kb << 7) + ((row ^ kb) << 4));
    }
    const uint32_t nterm0 = (uint32_t)(A_BYTES + ((wn * 8 + (quad >> 1)) << 10));
    uint32_t ktB[4];
    #pragma unroll
    for (int ks = 0; ks < 4; ++ks) {
        const int kb = 2 * ks + (quad & 1);
        ktB[ks] = (uint32_t)((kb << 7) + ((row ^ kb) << 4));
    }

    float acc[128];
    #pragma unroll
    for (int i = 0; i < 128; ++i) acc[i] = 0.0f;

    // ---- prologue: fill stages 0..2 ----
    #pragma unroll
    for (int s = 0; s < STAGES - 1; ++s) {
        const uint32_t st = sb + (uint32_t)(s * STAGE_BYTES);
        const __half* a = Ax + s * TILE_K;
        const __half* b = Wg + s * TILE_K;
        #pragma unroll
        for (int t = 0; t < 4; ++t) cp_async16(st + dA[t], a + oA[t]);
        #pragma unroll
        for (int t = 0; t < 8; ++t) cp_async16(st + dB[t], b + oB[t]);
        cp_commit();
    }

    // ---- mainloop ----
    #pragma unroll 1
    for (int i = 0; i < NITER; ++i) {
        cp_wait1();          // stages <= i+1 resident (own warp's copies)
        __syncthreads();     // cross-warp visibility; stage i-1 reads complete

        if (i + STAGES - 1 < NITER) {
            const int it = i + STAGES - 1;
            const uint32_t stw = sb + (uint32_t)((it & 3) * STAGE_BYTES);
            const __half* a = Ax + it * TILE_K;
            const __half* b = Wg + it * TILE_K;
            #pragma unroll
            for (int t = 0; t < 4; ++t) cp_async16(stw + dA[t], a + oA[t]);
            #pragma unroll
            for (int t = 0; t < 8; ++t) cp_async16(stw + dB[t], b + oB[t]);
        }
        cp_commit();

        const uint32_t st = sb + (uint32_t)((i & 3) * STAGE_BYTES);
        #pragma unroll
        for (int ks = 0; ks < 4; ++ks) {
            uint32_t afr[16], bfr[16];
            #pragma unroll
            for (int f = 0; f < 4; ++f)      // 4 m16-frags (64 rows)
                ldsm4(&afr[4 * f], st + mterm0 + (uint32_t)(f << 11) + ktA[ks]);
            #pragma unroll
            for (int gg = 0; gg < 4; ++gg)   // 8 n8-frags (64 B-rows)
                ldsm4(&bfr[4 * gg], st + nterm0 + (uint32_t)(gg << 11) + ktB[ks]);
            #pragma unroll
            for (int f = 0; f < 4; ++f) {
                #pragma unroll
                for (int nf = 0; nf < 8; ++nf) {
                    const int bo = ((nf >> 1) << 2) + ((nf & 1) << 1);
                    mma16(&acc[(f * 8 + nf) * 4], &afr[4 * f], bfr[bo], bfr[bo + 1]);
                }
            }
        }
    }

    __syncthreads();

    // ---- epilogue: silu(gate)*up, direct global stores ----
    const int gid = lane >> 2;
    const int tg  = lane & 3;
    #pragma unroll
    for (int f = 0; f < 4; ++f) {
        #pragma unroll
        for (int nf = 0; nf < 8; ++nf) {
            const float* c = &acc[(f * 8 + nf) * 4];
            const size_t mg1 = m0 + (size_t)(wm * 64 + f * 16 + gid);
            const int    jg  = n0 + wn * 32 + nf * 4 + tg;
            out[mg1 * IDIM + jg]       = silu_mul(c[0], c[1]);
            out[(mg1 + 8) * IDIM + jg] = silu_mul(c[2], c[3]);
        }
    }
}

// ---------------- launch ----------------
extern "C" void kernel_launch(void* const* d_in, const int* in_sizes, int n_in,
                              void* d_out, int out_size) {
    const float* x = (const float*)d_in[0];
    const float* w = (const float*)d_in[1];
    float* out = (float*)d_out;

    void* pxh = nullptr;
    void* pwh = nullptr;
    cudaGetSymbolAddress(&pxh, g_xh);
    cudaGetSymbolAddress(&pwh, g_wh);

    const int nx4 = (int)(((size_t)MTOT * HDIM) / 4);
    const int nw4 = (int)(((size_t)GQ * 2 * IDIM * HDIM) / 4);
    cvt_f16_kernel<<<2048, 256>>>((const float4*)x, (__half*)pxh, nx4,
                                  (const float4*)w, (__half*)pwh, nw4);

    cudaFuncSetAttribute(swiglu_kernel,
                         cudaFuncAttributeMaxDynamicSharedMemorySize, SMEM_TOTAL);
    swiglu_kernel<<<GQ * MT * NT, THREADS, SMEM_TOTAL>>>(
        (const __half*)pxh, (const __half*)pwh, out);
}